// round 2
// baseline (speedup 1.0000x reference)
#include <cuda_runtime.h>
#include <cuda_bf16.h>
#include <math.h>

// Problem constants
#define S   1024
#define E   512
#define H   512
#define G3  1536      // 3*H
#define D1  1024
#define R4  2048      // 4*H
#define VOC 50257

#define NDIR 4
#define BPD  37       // blocks per direction (4*37 = 148 blocks, 1 per SM)
#define RPB  14       // max h-rows per block (37*14 = 518 >= 512)
#define NTH  256

// ---------------- device scratch (no allocations allowed) ----------------
__device__ float g_x[S * E];                 // embedded sequence  [S][E]
__device__ float g_gi[NDIR * S * G3];        // input-side gates   [dir][S][3H]
__device__ float g_h[NDIR * 2 * H];          // double-buffered hidden state
__device__ float g_hfinal[NDIR * H];         // rep = [ctx_f, ctx_b, qry_f, qry_b]
__device__ float g_h1[D1];                   // dense1 output
__device__ int   g_ctr[NDIR * S];            // per-step arrival counters

// ---------------- sync primitives ----------------
__device__ __forceinline__ int ld_acquire(const int* p) {
    int v;
    asm volatile("ld.acquire.gpu.global.b32 %0, [%1];" : "=r"(v) : "l"(p) : "memory");
    return v;
}
__device__ __forceinline__ void red_release_add1(int* p) {
    asm volatile("red.release.gpu.global.add.s32 [%0], 1;" :: "l"(p) : "memory");
}

// ---------------- reset counters ----------------
__global__ void k_reset() {
    int i = blockIdx.x * blockDim.x + threadIdx.x;
    if (i < NDIR * S) g_ctr[i] = 0;
}

// ---------------- embedding gather (with int32/int64 sniffing) ----------------
__global__ void k_gather(const void* __restrict__ sent, const float* __restrict__ emb) {
    __shared__ int is64;
    if (threadIdx.x == 0) {
        const long long* p = (const long long*)sent;
        bool ok = true;
        #pragma unroll
        for (int i = 0; i < 4; i++) {
            long long v = p[i];
            if (v < 0 || v >= VOC) ok = false;
        }
        is64 = ok ? 1 : 0;
    }
    __syncthreads();
    int t = blockIdx.x;
    long long idx = is64 ? ((const long long*)sent)[t]
                         : (long long)((const int*)sent)[t];
    const float4* src = (const float4*)(emb + (size_t)idx * E);
    float4* dst = (float4*)(g_x + (size_t)t * E);
    for (int k = threadIdx.x; k < E / 4; k += blockDim.x) dst[k] = src[k];
}

// ---------------- gi GEMM: gi[d][t][r] = sum_k x[t][k]*Wih[d][r][k] + bih[d][r] ----
struct GemmArgs { const float* Wih[4]; const float* bih[4]; };

#define BM 64
#define BN 64
#define BK 16
__global__ void __launch_bounds__(256) k_gemm_gi(GemmArgs a) {
    int d = blockIdx.z;
    const float* __restrict__ Wih = a.Wih[d];
    const float* __restrict__ bih = a.bih[d];
    float* out = g_gi + (size_t)d * S * G3;

    __shared__ float sA[BK][BM + 4];   // x:   [k][t]
    __shared__ float sB[BK][BN + 4];   // Wih: [k][r]

    int t0 = blockIdx.x * BM;
    int r0 = blockIdx.y * BN;
    int tx = threadIdx.x & 15;         // t-direction
    int ty = threadIdx.x >> 4;         // r-direction

    float acc[4][4];
    #pragma unroll
    for (int i = 0; i < 4; i++)
        #pragma unroll
        for (int j = 0; j < 4; j++) acc[i][j] = 0.f;

    int lrow = threadIdx.x >> 2;        // 0..63
    int lk   = (threadIdx.x & 3) * 4;   // 0,4,8,12

    for (int k0 = 0; k0 < E; k0 += BK) {
        float4 va = *(const float4*)(g_x + (size_t)(t0 + lrow) * E + k0 + lk);
        float4 vb = *(const float4*)(Wih + (size_t)(r0 + lrow) * E + k0 + lk);
        sA[lk + 0][lrow] = va.x; sA[lk + 1][lrow] = va.y;
        sA[lk + 2][lrow] = va.z; sA[lk + 3][lrow] = va.w;
        sB[lk + 0][lrow] = vb.x; sB[lk + 1][lrow] = vb.y;
        sB[lk + 2][lrow] = vb.z; sB[lk + 3][lrow] = vb.w;
        __syncthreads();
        #pragma unroll
        for (int kk = 0; kk < BK; kk++) {
            float ar[4], br[4];
            #pragma unroll
            for (int i = 0; i < 4; i++) ar[i] = sA[kk][tx * 4 + i];
            #pragma unroll
            for (int j = 0; j < 4; j++) br[j] = sB[kk][ty * 4 + j];
            #pragma unroll
            for (int i = 0; i < 4; i++)
                #pragma unroll
                for (int j = 0; j < 4; j++) acc[i][j] = fmaf(ar[i], br[j], acc[i][j]);
        }
        __syncthreads();
    }
    #pragma unroll
    for (int i = 0; i < 4; i++) {
        int t = t0 + tx * 4 + i;
        #pragma unroll
        for (int j = 0; j < 4; j++) {
            int r = r0 + ty * 4 + j;
            out[(size_t)t * G3 + r] = acc[i][j] + __ldg(bih + r);
        }
    }
}

// ---------------- recurrent scan kernel ----------------
struct ScanArgs { const float* Whh[4]; const float* bhh[4]; };

__global__ void __launch_bounds__(NTH, 1) k_scan(ScanArgs a) {
    extern __shared__ float sw[];                    // [RPB*3*H] weights
    float* sgate = sw + RPB * 3 * H;                 // [RPB*3] gate partials

    const int blk   = blockIdx.x;
    const int d     = blk / BPD;
    const int b     = blk % BPD;
    const int hbase = b * RPB;
    const int nrows = min(RPB, H - hbase);
    const int nrg   = nrows * 3;

    const float* __restrict__ Whh = a.Whh[d];
    const float* __restrict__ bhh = a.bhh[d];
    const float* __restrict__ gi  = g_gi + (size_t)d * S * G3;
    int* ctr = g_ctr + d * S;
    float* hbank = g_h + d * 2 * H;

    const int tid  = threadIdx.x;
    const int lane = tid & 31;
    const int w    = tid >> 5;
    const bool back = (d & 1);

    // Stage Whh slice into shared: sw[(j*3+g)*H + k] = Whh[(g*H + hbase + j)*H + k]
    for (int x = tid; x < nrg * (H / 4); x += NTH) {
        int rg = x / (H / 4);
        int k4 = x - rg * (H / 4);
        int j = rg / 3, g = rg - j * 3;
        const float4 v = ((const float4*)(Whh + (size_t)(g * H + hbase + j) * H))[k4];
        ((float4*)(sw + (size_t)rg * H))[k4] = v;
    }
    // per-row biases + running hidden value (owned by thread j < nrows)
    float br = 0.f, bz = 0.f, bn = 0.f, hreg = 0.f;
    if (tid < nrows) {
        int i = hbase + tid;
        br = bhh[i]; bz = bhh[H + i]; bn = bhh[2 * H + i];
    }
    __syncthreads();

    for (int t = 0; t < S; ++t) {
        const int te = back ? (S - 1 - t) : t;

        // prefetch input-side gates (independent of h)
        float gr_ = 0.f, gz_ = 0.f, gn_ = 0.f;
        if (tid < nrows) {
            const float* grow = gi + (size_t)te * G3 + hbase + tid;
            gr_ = __ldg(grow);
            gz_ = __ldg(grow + H);
            gn_ = __ldg(grow + 2 * H);
        }

        // wait for step t-1 barrier (all blocks of this direction)
        if (t > 0) {
            if (tid == 0) {
                while (ld_acquire(&ctr[t - 1]) < BPD) { }
            }
            __syncthreads();
        }

        // load h (bypass L1 — other SMs wrote it)
        float hk[16];
        if (t == 0) {
            #pragma unroll
            for (int kk = 0; kk < 16; kk++) hk[kk] = 0.f;
        } else {
            const float* hcur = hbank + (t & 1) * H;
            #pragma unroll
            for (int kk = 0; kk < 16; kk++) hk[kk] = __ldcg(hcur + lane + 32 * kk);
        }

        // gh partials: warp w handles row-gates w, w+8, ...
        for (int rg = w; rg < nrg; rg += 8) {
            const float* wr = sw + (size_t)rg * H;
            float acc = 0.f;
            #pragma unroll
            for (int kk = 0; kk < 16; kk++)
                acc = fmaf(wr[lane + 32 * kk], hk[kk], acc);
            #pragma unroll
            for (int off = 16; off > 0; off >>= 1)
                acc += __shfl_xor_sync(0xFFFFFFFFu, acc, off);
            if (lane == 0) sgate[rg] = acc;
        }
        __syncthreads();

        // gate math + h update (thread j owns h row hbase+j)
        if (tid < nrows) {
            float ghr = sgate[tid * 3 + 0] + br;
            float ghz = sgate[tid * 3 + 1] + bz;
            float ghn = sgate[tid * 3 + 2] + bn;
            float r = 1.f / (1.f + expf(-(gr_ + ghr)));
            float z = 1.f / (1.f + expf(-(gz_ + ghz)));
            float n = tanhf(gn_ + r * ghn);
            float hnew = (1.f - z) * n + z * hreg;
            hreg = hnew;
            hbank[((t + 1) & 1) * H + hbase + tid] = hnew;
            if (t == S - 1) g_hfinal[d * H + hbase + tid] = hnew;
            __threadfence();
        }
        __syncthreads();
        if (tid == 0) red_release_add1(&ctr[t]);
    }
}

// ---------------- dense1: h1 = relu(d1_w @ rep + d1_b) ----------------
__global__ void __launch_bounds__(256) k_dense1(const float* __restrict__ d1w,
                                                const float* __restrict__ d1b) {
    int warp = threadIdx.x >> 5, lane = threadIdx.x & 31;
    int row = blockIdx.x * 8 + warp;          // grid 128 -> 1024 rows
    const float* wr = d1w + (size_t)row * R4;
    float acc = 0.f;
    #pragma unroll 8
    for (int k = lane; k < R4; k += 32)
        acc = fmaf(wr[k], g_hfinal[k], acc);
    #pragma unroll
    for (int off = 16; off > 0; off >>= 1)
        acc += __shfl_xor_sync(0xFFFFFFFFu, acc, off);
    if (lane == 0) g_h1[row] = fmaxf(acc + d1b[row], 0.f);
}

// ---------------- dense2: out = sigmoid(d2_w . h1 + d2_b) ----------------
__global__ void __launch_bounds__(1024) k_dense2(const float* __restrict__ d2w,
                                                 const float* __restrict__ d2b,
                                                 float* __restrict__ out) {
    __shared__ float red[32];
    int tid = threadIdx.x, lane = tid & 31;
    float v = g_h1[tid] * d2w[tid];
    #pragma unroll
    for (int off = 16; off > 0; off >>= 1)
        v += __shfl_xor_sync(0xFFFFFFFFu, v, off);
    if (lane == 0) red[tid >> 5] = v;
    __syncthreads();
    if (tid < 32) {
        float s = red[tid];
        #pragma unroll
        for (int off = 16; off > 0; off >>= 1)
            s += __shfl_xor_sync(0xFFFFFFFFu, s, off);
        if (tid == 0) out[0] = 1.f / (1.f + expf(-(s + d2b[0])));
    }
}

// ---------------- launch ----------------
extern "C" void kernel_launch(void* const* d_in, const int* in_sizes, int n_in,
                              void* d_out, int out_size) {
    const void*  sent = d_in[0];
    const float* emb  = (const float*)d_in[1];

    GemmArgs ga; ScanArgs sa;
    for (int d = 0; d < 4; d++) {
        ga.Wih[d] = (const float*)d_in[2 + 4 * d + 0];
        sa.Whh[d] = (const float*)d_in[2 + 4 * d + 1];
        ga.bih[d] = (const float*)d_in[2 + 4 * d + 2];
        sa.bhh[d] = (const float*)d_in[2 + 4 * d + 3];
    }
    const float* d1w = (const float*)d_in[18];
    const float* d1b = (const float*)d_in[19];
    const float* d2w = (const float*)d_in[20];
    const float* d2b = (const float*)d_in[21];
    float* out = (float*)d_out;

    static const size_t scan_smem = (size_t)(RPB * 3 * H + 64) * sizeof(float);
    cudaFuncSetAttribute(k_scan, cudaFuncAttributeMaxDynamicSharedMemorySize,
                         (int)scan_smem);

    k_reset<<<(NDIR * S + 255) / 256, 256>>>();
    k_gather<<<S, 128>>>(sent, emb);
    k_gemm_gi<<<dim3(S / BM, G3 / BN, NDIR), 256>>>(ga);
    k_scan<<<NDIR * BPD, NTH, scan_smem>>>(sa);
    k_dense1<<<D1 / 8, 256>>>(d1w, d1b);
    k_dense2<<<1, 1024>>>(d2w, d2b, out);
}